// round 16
// baseline (speedup 1.0000x reference)
#include <cuda_runtime.h>
#include <math.h>
#include <stdint.h>

#define AA 3072          // A = BS * IA
#define DD 2048          // D = BS * (IA-1)
#define NB 1024          // BS
#define NBLK 296         // persistent grid: 2 CTAs/SM * 148 SMs
#define NWARP (NBLK * 8) // 2368 global warps

// partial-dot ping-pong buffers (max units per layer = 3072*3 = 9216)
__device__ float g_pA[9216];
__device__ float g_pB[9216];
__device__ unsigned g_bar;    // zero-init; reset at end of every run
__device__ unsigned g_exit;

// ---------------------------------------------------------------------------
// grid-wide barrier (all NBLK blocks resident): release/acquire
// ---------------------------------------------------------------------------
__device__ __forceinline__ void grid_bar(int tid, unsigned target) {
    __syncthreads();
    if (tid == 0) {
        asm volatile("red.release.gpu.global.add.u32 [%0], 1;"
                     :: "l"(&g_bar) : "memory");
        unsigned v;
        do {
            asm volatile("ld.acquire.gpu.global.u32 %0, [%1];"
                         : "=r"(v) : "l"(&g_bar));
        } while (v < target);
    }
    __syncthreads();
}

template<int ACT>
__device__ __forceinline__ float act_apply(float h) {
    if (ACT == 1) return tanhf(h);
    if (ACT == 2) return h - tanhf(h);
    return h;
}

// ---------------------------------------------------------------------------
// chunked partial GEMV: each unit = 1024-float chunk of one row (4 KB).
// unit u -> row = u/NCH, chunk = u%NCH. Warp computes partial dot of chunk
// against sx[chunk*1024 ...] and stores the scalar to part[u].
// Units double-buffered: next unit's 8 LDG.128 issue before current FMAs.
// ---------------------------------------------------------------------------
template<int NCH>
__device__ __forceinline__ void layer_chunks(const float* __restrict__ W,
                                             int ROWS,
                                             const float* __restrict__ sx,
                                             float* __restrict__ part,
                                             int gw, int lane)
{
    const int NU = ROWS * NCH;
    int u = gw;
    if (u >= NU) return;

    const float4* __restrict__ sx4 = reinterpret_cast<const float4*>(sx);
    float4 buf[2][8];

    {   // prologue: load unit u
        const int row = u / NCH, ch = u % NCH;
        const float4* W4 = reinterpret_cast<const float4*>(
            W + (size_t)row * (NCH * 1024) + ch * 1024);
        #pragma unroll
        for (int t = 0; t < 8; ++t) buf[0][t] = __ldcs(&W4[lane + 32 * t]);
    }

    int cur = 0;
    while (true) {
        const int un = u + NWARP;
        if (un < NU) {   // prefetch next unit into alternate buffer
            const int row = un / NCH, ch = un % NCH;
            const float4* W4 = reinterpret_cast<const float4*>(
                W + (size_t)row * (NCH * 1024) + ch * 1024);
            #pragma unroll
            for (int t = 0; t < 8; ++t) buf[cur ^ 1][t] = __ldcs(&W4[lane + 32 * t]);
        }

        const int ch = u % NCH;
        const float4* sxc = sx4 + ch * 256;   // 1024 floats = 256 float4
        float a0 = 0.f, a1 = 0.f, a2 = 0.f, a3 = 0.f;
        #pragma unroll
        for (int t = 0; t < 8; ++t) {
            float4 v = sxc[lane + 32 * t];
            a0 = fmaf(buf[cur][t].x, v.x, a0);
            a1 = fmaf(buf[cur][t].y, v.y, a1);
            a2 = fmaf(buf[cur][t].z, v.z, a2);
            a3 = fmaf(buf[cur][t].w, v.w, a3);
        }
        float acc = (a0 + a1) + (a2 + a3);
        #pragma unroll
        for (int off = 16; off; off >>= 1)
            acc += __shfl_xor_sync(0xFFFFFFFFu, acc, off);
        if (lane == 0) part[u] = acc;

        if (un >= NU) break;
        u = un; cur ^= 1;
    }
}

// ---------------------------------------------------------------------------
// staging combine: build sx[r] = ACT( sum_ch part[r*NCH+ch] + b[r] ) for the
// PRODUCING layer's partials; optionally mirror to gmem (block 0 only).
// ---------------------------------------------------------------------------
template<int ACT, int NCH>
__device__ __forceinline__ void stage_combine(const float* __restrict__ part,
                                              const float* __restrict__ b,
                                              float* __restrict__ sx, int n,
                                              int tid, float* __restrict__ gout)
{
    for (int r = tid; r < n; r += 256) {
        float p = part[r * NCH] + part[r * NCH + 1];
        if (NCH == 3) p += part[r * NCH + 2];
        float v = act_apply<ACT>(p + __ldg(&b[r]));
        sx[r] = v;
        if (gout) gout[r] = v;
    }
    __syncthreads();
}

// ---------------------------------------------------------------------------
// warp-local pdist slice (no barriers), streaming stores
// ---------------------------------------------------------------------------
template<int DIMS>
__device__ __forceinline__ void pdist_warp(const float* __restrict__ s,
                                           float* __restrict__ outp,
                                           int gw, int lane)
{
    for (int idx = gw * 32 + lane; idx < NB * NB; idx += NWARP * 32) {
        const int i = idx >> 10;
        const int j = idx & (NB - 1);
        float d2 = 0.f;
        #pragma unroll
        for (int k = 0; k < DIMS; ++k) {
            float d = s[i * DIMS + k] - s[j * DIMS + k];
            d2 = fmaf(d, d, d2);
        }
        __stcs(&outp[idx], sqrtf(d2));
    }
}

// ---------------------------------------------------------------------------
// the whole network, persistent, chunk-balanced streaming
// ---------------------------------------------------------------------------
__global__ void __launch_bounds__(256, 2)
fused_net(const float* __restrict__ x,
          const float* __restrict__ ew1, const float* __restrict__ eb1,
          const float* __restrict__ ew2, const float* __restrict__ eb2,
          const float* __restrict__ ew3, const float* __restrict__ eb3,
          const float* __restrict__ ew4, const float* __restrict__ eb4,
          const float* __restrict__ dw1, const float* __restrict__ db1,
          const float* __restrict__ dw2, const float* __restrict__ db2,
          const float* __restrict__ dw3, const float* __restrict__ db3,
          const float* __restrict__ dw4, const float* __restrict__ db4,
          float* __restrict__ out)
{
    __shared__ float sx[AA];    // 12 KB layer input

    const int tid  = threadIdx.x;
    const int bid  = blockIdx.x;
    const int lane = tid & 31;
    const int gw   = bid * 8 + (tid >> 5);

    float* out_main = out;                      // 3072
    float* out_ind  = out + AA;                 // 1024*1024
    float* out_lat  = out + AA + NB * NB;       // 1024*1024
    float* y        = out + AA + 2 * NB * NB;   // 2048 (lat_repr)

    // ---- L1: stage x directly; chunks -> pA; bubble: pdist on x ----
    {
        const float4* xg4 = reinterpret_cast<const float4*>(x);
        float4* sx4 = reinterpret_cast<float4*>(sx);
        for (int k = tid; k < AA / 4; k += 256) sx4[k] = __ldg(&xg4[k]);
        __syncthreads();
    }
    layer_chunks<3>(ew1, AA, sx, g_pA, gw, lane);
    pdist_warp<3>(sx, out_ind, gw, lane);
    grid_bar(tid, NBLK * 1);

    // ---- L2: consume pA (eb1, tanh); chunks -> pB ----
    stage_combine<1, 3>(g_pA, eb1, sx, AA, tid, nullptr);
    layer_chunks<3>(ew2, AA, sx, g_pB, gw, lane);
    grid_bar(tid, NBLK * 2);

    // ---- L3: consume pB (eb2, tanh); chunks -> pA ----
    stage_combine<1, 3>(g_pB, eb2, sx, AA, tid, nullptr);
    layer_chunks<3>(ew3, AA, sx, g_pA, gw, lane);
    grid_bar(tid, NBLK * 3);

    // ---- L4: consume pA (eb3, none); chunks (2048 rows) -> pB ----
    stage_combine<0, 3>(g_pA, eb3, sx, AA, tid, nullptr);
    layer_chunks<3>(ew4, DD, sx, g_pB, gw, lane);
    grid_bar(tid, NBLK * 4);

    // ---- L5: consume pB (eb4, tanhshrink) => y (2048); block0 mirrors to
    //      gmem; chunks (COLS=2048, NCH=2) -> pA; bubble: pdist on y ----
    stage_combine<2, 3>(g_pB, eb4, sx, DD, tid, (bid == 0) ? y : nullptr);
    layer_chunks<2>(dw1, AA, sx, g_pA, gw, lane);
    pdist_warp<2>(sx, out_lat, gw, lane);
    grid_bar(tid, NBLK * 5);

    // ---- L6: consume pA (db1, tanh, NCH=2); chunks -> pB ----
    stage_combine<1, 2>(g_pA, db1, sx, AA, tid, nullptr);
    layer_chunks<3>(dw2, AA, sx, g_pB, gw, lane);
    grid_bar(tid, NBLK * 6);

    // ---- L7: consume pB (db2, tanh); chunks -> pA ----
    stage_combine<1, 3>(g_pB, db2, sx, AA, tid, nullptr);
    layer_chunks<3>(dw3, AA, sx, g_pA, gw, lane);
    grid_bar(tid, NBLK * 7);

    // ---- L8: consume pA (db3, none); chunks -> pB ----
    stage_combine<0, 3>(g_pA, db3, sx, AA, tid, nullptr);
    layer_chunks<3>(dw4, AA, sx, g_pB, gw, lane);
    grid_bar(tid, NBLK * 8);

    // ---- final: out_main[r] = tanh( sum pB + db4[r] ) ----
    {
        const int r = bid * 256 + tid;
        if (r < AA) {
            float p = g_pB[r * 3] + g_pB[r * 3 + 1] + g_pB[r * 3 + 2];
            out_main[r] = tanhf(p + db4[r]);
        }
    }

    // exit: last block resets barrier counters for next replay
    __syncthreads();
    if (tid == 0) {
        unsigned done = atomicAdd(&g_exit, 1u);
        if (done == NBLK - 1) {
            g_bar  = 0;
            g_exit = 0;
            __threadfence();
        }
    }
}

// ---------------------------------------------------------------------------
extern "C" void kernel_launch(void* const* d_in, const int* in_sizes, int n_in,
                              void* d_out, int out_size)
{
    (void)in_sizes; (void)n_in; (void)out_size;

    fused_net<<<NBLK, 256>>>(
        (const float*)d_in[0],
        (const float*)d_in[1],  (const float*)d_in[2],
        (const float*)d_in[3],  (const float*)d_in[4],
        (const float*)d_in[5],  (const float*)d_in[6],
        (const float*)d_in[7],  (const float*)d_in[8],
        (const float*)d_in[9],  (const float*)d_in[10],
        (const float*)d_in[11], (const float*)d_in[12],
        (const float*)d_in[13], (const float*)d_in[14],
        (const float*)d_in[15], (const float*)d_in[16],
        (float*)d_out);
}

// round 17
// speedup vs baseline: 1.0531x; 1.0531x over previous
#include <cuda_runtime.h>
#include <math.h>
#include <stdint.h>

#define AA 3072          // A = BS * IA
#define DD 2048          // D = BS * (IA-1)
#define NB 1024          // BS
#define NBLK 296         // persistent grid: 2 CTAs/SM * 148 SMs
#define NWARP (NBLK * 8) // 2368 global warps
#define NSPLIT (AA - NWARP)        // 704 rows handled as halves
#define NHALF  (2 * NSPLIT)        // 1408 half-units

__device__ float g_fullA[NWARP], g_fullB[NWARP];   // full-row results (act applied)
__device__ float g_halfA[NHALF], g_halfB[NHALF];   // half-row partials (raw)
__device__ unsigned g_bar;
__device__ unsigned g_exit;

// ---------------------------------------------------------------------------
__device__ __forceinline__ void grid_bar(int tid, unsigned target) {
    __syncthreads();
    if (tid == 0) {
        asm volatile("red.release.gpu.global.add.u32 [%0], 1;"
                     :: "l"(&g_bar) : "memory");
        unsigned v;
        do {
            asm volatile("ld.acquire.gpu.global.u32 %0, [%1];"
                         : "=r"(v) : "l"(&g_bar));
        } while (v < target);
    }
    __syncthreads();
}

template<int ACT>
__device__ __forceinline__ float act_apply(float h) {
    if (ACT == 1) return tanhf(h);
    if (ACT == 2) return h - tanhf(h);
    return h;
}

// ---------------------------------------------------------------------------
// full-row dot (R15-proven): 8-deep double-buffered static pipeline
// ---------------------------------------------------------------------------
template<int ACT, int COLS>
__device__ __forceinline__ void dot_row(const float* __restrict__ W,
                                        const float* __restrict__ sx,
                                        const float* __restrict__ b,
                                        float* __restrict__ y,
                                        int row, int lane)
{
    constexpr int NBATCH = COLS / 4 / 32 / 8;   // 3 (3072) or 2 (2048)
    const float4* __restrict__ W4 =
        reinterpret_cast<const float4*>(W + (size_t)row * COLS);
    const float4* __restrict__ sx4 = reinterpret_cast<const float4*>(sx);

    float4 buf[2][8];
    #pragma unroll
    for (int t = 0; t < 8; ++t)
        buf[0][t] = __ldcs(&W4[lane + 32 * t]);

    float a0 = 0.f, a1 = 0.f, a2 = 0.f, a3 = 0.f;
    #pragma unroll
    for (int bt = 0; bt < NBATCH; ++bt) {
        const int cur = bt & 1;
        if (bt + 1 < NBATCH) {
            #pragma unroll
            for (int t = 0; t < 8; ++t)
                buf[cur ^ 1][t] = __ldcs(&W4[lane + 32 * (8 * (bt + 1) + t)]);
        }
        #pragma unroll
        for (int t = 0; t < 8; ++t) {
            float4 v = sx4[lane + 32 * (8 * bt + t)];
            a0 = fmaf(buf[cur][t].x, v.x, a0);
            a1 = fmaf(buf[cur][t].y, v.y, a1);
            a2 = fmaf(buf[cur][t].z, v.z, a2);
            a3 = fmaf(buf[cur][t].w, v.w, a3);
        }
    }
    float acc = (a0 + a1) + (a2 + a3);
    #pragma unroll
    for (int off = 16; off; off >>= 1)
        acc += __shfl_xor_sync(0xFFFFFFFFu, acc, off);

    if (lane == 0)
        y[row] = act_apply<ACT>(acc + b[row]);
}

// ---------------------------------------------------------------------------
// half-row partial dot: F4 = per-lane float4 count (12 for 3072-col halves,
// 8 for 2048-col halves); 4-deep static double-buffered pipeline; raw partial.
// ---------------------------------------------------------------------------
template<int F4>
__device__ __forceinline__ void dot_half(const float* __restrict__ Wp,
                                         const float* __restrict__ sxc,
                                         float* __restrict__ dst, int lane)
{
    constexpr int NBATCH = F4 / 4;              // 3 or 2
    const float4* __restrict__ W4 = reinterpret_cast<const float4*>(Wp);
    const float4* __restrict__ s4 = reinterpret_cast<const float4*>(sxc);

    float4 buf[2][4];
    #pragma unroll
    for (int t = 0; t < 4; ++t)
        buf[0][t] = __ldcs(&W4[lane + 32 * t]);

    float a0 = 0.f, a1 = 0.f, a2 = 0.f, a3 = 0.f;
    #pragma unroll
    for (int bt = 0; bt < NBATCH; ++bt) {
        const int cur = bt & 1;
        if (bt + 1 < NBATCH) {
            #pragma unroll
            for (int t = 0; t < 4; ++t)
                buf[cur ^ 1][t] = __ldcs(&W4[lane + 32 * (4 * (bt + 1) + t)]);
        }
        #pragma unroll
        for (int t = 0; t < 4; ++t) {
            float4 v = s4[lane + 32 * (4 * bt + t)];
            a0 = fmaf(buf[cur][t].x, v.x, a0);
            a1 = fmaf(buf[cur][t].y, v.y, a1);
            a2 = fmaf(buf[cur][t].z, v.z, a2);
            a3 = fmaf(buf[cur][t].w, v.w, a3);
        }
    }
    float acc = (a0 + a1) + (a2 + a3);
    #pragma unroll
    for (int off = 16; off; off >>= 1)
        acc += __shfl_xor_sync(0xFFFFFFFFu, acc, off);
    if (lane == 0) *dst = acc;
}

// ---------------------------------------------------------------------------
// split layer (3072 rows or 3072x2048): every warp does row gw (full);
// warps < NHALF additionally do one half of rows 2368..3071.
// ---------------------------------------------------------------------------
template<int ACT, int COLS>
__device__ __forceinline__ void layer_split(const float* __restrict__ W,
                                            const float* __restrict__ b,
                                            const float* __restrict__ sx,
                                            float* __restrict__ fullout,
                                            float* __restrict__ halfout,
                                            int gw, int lane)
{
    dot_row<ACT, COLS>(W, sx, b, fullout, gw, lane);      // gw < 2368 < 3072
    if (gw < NHALF) {
        const int row = NWARP + (gw >> 1);
        const int h   = gw & 1;
        constexpr int HALF = COLS / 2;
        dot_half<HALF / 128>(W + (size_t)row * COLS + h * HALF,
                             sx + h * HALF, &halfout[gw], lane);
    }
}

// staging for a split producer: full rows already final; split rows combined
// here with the PRODUCER's bias + activation.
template<int ACT>
__device__ __forceinline__ void stage_split(const float* __restrict__ full,
                                            const float* __restrict__ half,
                                            const float* __restrict__ b,
                                            float* __restrict__ sx, int tid)
{
    for (int r = tid; r < AA; r += 256) {
        float v;
        if (r < NWARP) v = full[r];
        else {
            const int i = r - NWARP;
            v = act_apply<ACT>(half[2 * i] + half[2 * i + 1] + __ldg(&b[r]));
        }
        sx[r] = v;
    }
    __syncthreads();
}

// ---------------------------------------------------------------------------
template<int DIMS>
__device__ __forceinline__ void pdist_warp(const float* __restrict__ s,
                                           float* __restrict__ outp,
                                           int gw, int lane)
{
    for (int idx = gw * 32 + lane; idx < NB * NB; idx += NWARP * 32) {
        const int i = idx >> 10;
        const int j = idx & (NB - 1);
        float d2 = 0.f;
        #pragma unroll
        for (int k = 0; k < DIMS; ++k) {
            float d = s[i * DIMS + k] - s[j * DIMS + k];
            d2 = fmaf(d, d, d2);
        }
        __stcs(&outp[idx], sqrtf(d2));
    }
}

// ---------------------------------------------------------------------------
__global__ void __launch_bounds__(256, 2)
fused_net(const float* __restrict__ x,
          const float* __restrict__ ew1, const float* __restrict__ eb1,
          const float* __restrict__ ew2, const float* __restrict__ eb2,
          const float* __restrict__ ew3, const float* __restrict__ eb3,
          const float* __restrict__ ew4, const float* __restrict__ eb4,
          const float* __restrict__ dw1, const float* __restrict__ db1,
          const float* __restrict__ dw2, const float* __restrict__ db2,
          const float* __restrict__ dw3, const float* __restrict__ db3,
          const float* __restrict__ dw4, const float* __restrict__ db4,
          float* __restrict__ out)
{
    __shared__ float sx[AA];

    const int tid  = threadIdx.x;
    const int bid  = blockIdx.x;
    const int lane = tid & 31;
    const int gw   = bid * 8 + (tid >> 5);

    float* out_main = out;                      // 3072
    float* out_ind  = out + AA;                 // 1024*1024
    float* out_lat  = out + AA + NB * NB;       // 1024*1024
    float* y        = out + AA + 2 * NB * NB;   // 2048 (lat_repr)

    // ---- L1: stage x; split layer ew1 (tanh,eb1) -> set A; pdist(x) ----
    {
        const float4* xg4 = reinterpret_cast<const float4*>(x);
        float4* sx4 = reinterpret_cast<float4*>(sx);
        for (int k = tid; k < AA / 4; k += 256) sx4[k] = __ldg(&xg4[k]);
        __syncthreads();
    }
    layer_split<1, AA>(ew1, eb1, sx, g_fullA, g_halfA, gw, lane);
    pdist_warp<3>(sx, out_ind, gw, lane);
    grid_bar(tid, NBLK * 1);

    // ---- L2: stage A (eb1,tanh); ew2 -> set B ----
    stage_split<1>(g_fullA, g_halfA, eb1, sx, tid);
    layer_split<1, AA>(ew2, eb2, sx, g_fullB, g_halfB, gw, lane);
    grid_bar(tid, NBLK * 2);

    // ---- L3: stage B (eb2,tanh); ew3 -> set A ----
    stage_split<1>(g_fullB, g_halfB, eb2, sx, tid);
    layer_split<0, AA>(ew3, eb3, sx, g_fullA, g_halfA, gw, lane);
    grid_bar(tid, NBLK * 3);

    // ---- L4: stage A (eb3,none); ew4 (2048 rows, all full) -> y direct ----
    stage_split<0>(g_fullA, g_halfA, eb3, sx, tid);
    if (gw < DD)
        dot_row<2, AA>(ew4, sx, eb4, y, gw, lane);    // tanhshrink
    grid_bar(tid, NBLK * 4);

    // ---- L5: stage y from gmem; dw1 (COLS=2048) -> set A; pdist(y) ----
    {
        const float4* yg4 = reinterpret_cast<const float4*>(y);
        float4* sx4 = reinterpret_cast<float4*>(sx);
        for (int k = tid; k < DD / 4; k += 256) sx4[k] = __ldg(&yg4[k]);
        __syncthreads();
    }
    layer_split<1, DD>(dw1, db1, sx, g_fullA, g_halfA, gw, lane);
    pdist_warp<2>(sx, out_lat, gw, lane);
    grid_bar(tid, NBLK * 5);

    // ---- L6: stage A (db1,tanh); dw2 -> set B ----
    stage_split<1>(g_fullA, g_halfA, db1, sx, tid);
    layer_split<1, AA>(dw2, db2, sx, g_fullB, g_halfB, gw, lane);
    grid_bar(tid, NBLK * 6);

    // ---- L7: stage B (db2,tanh); dw3 -> set A ----
    stage_split<1>(g_fullB, g_halfB, db2, sx, tid);
    layer_split<0, AA>(dw3, db3, sx, g_fullA, g_halfA, gw, lane);
    grid_bar(tid, NBLK * 7);

    // ---- L8: stage A (db3,none); dw4 (tanh,db4): full rows -> out_main
    //      directly, split rows -> halfB ----
    stage_split<0>(g_fullA, g_halfA, db3, sx, tid);
    layer_split<1, AA>(dw4, db4, sx, out_main, g_halfB, gw, lane);
    grid_bar(tid, NBLK * 8);

    // ---- final: combine split rows of L8 ----
    {
        const int i = bid * 256 + tid;
        if (i < NSPLIT) {
            const int r = NWARP + i;
            out_main[r] = tanhf(g_halfB[2 * i] + g_halfB[2 * i + 1] + db4[r]);
        }
    }

    // exit: last block resets barrier counters for next replay
    __syncthreads();
    if (tid == 0) {
        unsigned done = atomicAdd(&g_exit, 1u);
        if (done == NBLK - 1) {
            g_bar  = 0;
            g_exit = 0;
            __threadfence();
        }
    }
}

// ---------------------------------------------------------------------------
extern "C" void kernel_launch(void* const* d_in, const int* in_sizes, int n_in,
                              void* d_out, int out_size)
{
    (void)in_sizes; (void)n_in; (void)out_size;

    fused_net<<<NBLK, 256>>>(
        (const float*)d_in[0],
        (const float*)d_in[1],  (const float*)d_in[2],
        (const float*)d_in[3],  (const float*)d_in[4],
        (const float*)d_in[5],  (const float*)d_in[6],
        (const float*)d_in[7],  (const float*)d_in[8],
        (const float*)d_in[9],  (const float*)d_in[10],
        (const float*)d_in[11], (const float*)d_in[12],
        (const float*)d_in[13], (const float*)d_in[14],
        (const float*)d_in[15], (const float*)d_in[16],
        (float*)d_out);
}